// round 4
// baseline (speedup 1.0000x reference)
#include <cuda_runtime.h>
#include <math.h>

#define BB 64
#define TT 2048
#define HH 512
#define QQ 512
#define NCHUNK 32
#define CHUNK (TT / NCHUNK)   // 64 rows per chunk

// Scratch (allocation-free rule: __device__ globals)
__device__ __align__(16) float g_v[BB * HH];             // v[b] = W^T q[b] (final)
__device__ float g_pm[BB * NCHUNK];                      // per-chunk running max
__device__ float g_ps[BB * NCHUNK];                      // per-chunk exp-sum
__device__ __align__(16) float g_pctx[BB * NCHUNK * HH]; // per-chunk weighted ctx (4 MB)

// ---------------------------------------------------------------------------
// tgt_index dtype detection (int64 vs int32) — verified working.
// ---------------------------------------------------------------------------
__device__ __forceinline__ int detect_is64(const int* __restrict__ tgt_raw) {
    int odd_or = 0;
#pragma unroll
    for (int i = 1; i < 2 * BB; i += 2) odd_or |= tgt_raw[i];
    return odd_or == 0;
}
__device__ __forceinline__ int load_len(const int* __restrict__ tgt_raw, int b, int is64) {
    return (is64 ? tgt_raw[2 * b] : tgt_raw[b]) + 1;
}

// ---------------------------------------------------------------------------
// Kernel 1: v[b,h] = sum_q query[b,q] * W[q,h], fully reduced in-kernel.
// Grid (HH/128, BB/4), 256 threads (8 warps). Warp w owns q-slice [64w,64w+64);
// lane owns one float4 of the 128-float h-tile, for 4 batches (16 indep accs).
// Per iter: 1 coalesced LDG.128 of W + 16 FMA. Then smem tree-reduce.
// ---------------------------------------------------------------------------
#define K1_BGRP  4
#define K1_HT    128           // h-tile floats
#define K1_QS    64            // q rows per warp

__global__ __launch_bounds__(256) void k1_proj(const float* __restrict__ query,
                                               const float* __restrict__ W) {
    const int h4_0 = blockIdx.x * (K1_HT / 4);   // float4 base of h-tile
    const int b0   = blockIdx.y * K1_BGRP;
    const int tid  = threadIdx.x, w = tid >> 5, lane = tid & 31;

    __shared__ float sq[K1_BGRP][QQ];            // 8 KB: 4 query rows
    for (int i = tid; i < K1_BGRP * QQ; i += 256)
        sq[i >> 9][i & 511] = query[(b0 + (i >> 9)) * QQ + (i & 511)];
    __syncthreads();

    const float4* W4 = (const float4*)W + (size_t)(w * K1_QS) * (HH / 4) + h4_0 + lane;
    float4 a0 = make_float4(0.f, 0.f, 0.f, 0.f), a1 = a0, a2 = a0, a3 = a0;

    const int qb = w * K1_QS;
#pragma unroll 8
    for (int q = 0; q < K1_QS; q++) {
        const float4 wv = W4[q * (HH / 4)];
        const float q0 = sq[0][qb + q], q1 = sq[1][qb + q];
        const float q2 = sq[2][qb + q], q3 = sq[3][qb + q];
        a0.x = fmaf(wv.x, q0, a0.x); a0.y = fmaf(wv.y, q0, a0.y);
        a0.z = fmaf(wv.z, q0, a0.z); a0.w = fmaf(wv.w, q0, a0.w);
        a1.x = fmaf(wv.x, q1, a1.x); a1.y = fmaf(wv.y, q1, a1.y);
        a1.z = fmaf(wv.z, q1, a1.z); a1.w = fmaf(wv.w, q1, a1.w);
        a2.x = fmaf(wv.x, q2, a2.x); a2.y = fmaf(wv.y, q2, a2.y);
        a2.z = fmaf(wv.z, q2, a2.z); a2.w = fmaf(wv.w, q2, a2.w);
        a3.x = fmaf(wv.x, q3, a3.x); a3.y = fmaf(wv.y, q3, a3.y);
        a3.z = fmaf(wv.z, q3, a3.z); a3.w = fmaf(wv.w, q3, a3.w);
    }
    __syncthreads();                              // sq dead, reuse smem

    __shared__ __align__(16) float4 sred[8][K1_BGRP][32];   // 16 KB
    sred[w][0][lane] = a0; sred[w][1][lane] = a1;
    sred[w][2][lane] = a2; sred[w][3][lane] = a3;
    __syncthreads();

    if (tid < K1_BGRP * 32) {                     // 128 threads: (batch, lane)
        const int bt = tid >> 5, ln = tid & 31;
        float4 r = sred[0][bt][ln];
#pragma unroll
        for (int i = 1; i < 8; i++) {
            const float4 p = sred[i][bt][ln];
            r.x += p.x; r.y += p.y; r.z += p.z; r.w += p.w;
        }
        ((float4*)g_v)[(b0 + bt) * (HH / 4) + h4_0 + ln] = r;
    }
}

// ---------------------------------------------------------------------------
// Kernel 2: flash pass over one (chunk, batch). 8 warps, warp-per-row strided
// (stride 8). Depth-2 software pipeline: 8 float4 loads in flight per warp.
// ---------------------------------------------------------------------------
__device__ __forceinline__ float dot4(float4 a, float4 b) {
    return a.x * b.x + a.y * b.y + a.z * b.z + a.w * b.w;
}

#define LOAD_ROW(d0, d1, d2, d3, tt)                                   \
    { const float4* r_ = ebase + (size_t)(tt) * (HH / 4);              \
      d0 = r_[lane]; d1 = r_[lane + 32]; d2 = r_[lane + 64]; d3 = r_[lane + 96]; }

#define PROCESS_ROW(E0, E1, E2, E3)                                              \
    {                                                                            \
        float d = dot4(E0, va) + dot4(E1, vb) + dot4(E2, vc) + dot4(E3, vd);     \
        d += __shfl_xor_sync(0xFFFFFFFFu, d, 16);                                \
        d += __shfl_xor_sync(0xFFFFFFFFu, d, 8);                                 \
        d += __shfl_xor_sync(0xFFFFFFFFu, d, 4);                                 \
        d += __shfl_xor_sync(0xFFFFFFFFu, d, 2);                                 \
        d += __shfl_xor_sync(0xFFFFFFFFu, d, 1);                                 \
        if (d > m) {                                                             \
            const float alpha = __expf(m - d);                                   \
            m = d;                                                               \
            s = s * alpha + 1.f;                                                 \
            c0.x = c0.x * alpha + E0.x; c0.y = c0.y * alpha + E0.y;              \
            c0.z = c0.z * alpha + E0.z; c0.w = c0.w * alpha + E0.w;              \
            c1.x = c1.x * alpha + E1.x; c1.y = c1.y * alpha + E1.y;              \
            c1.z = c1.z * alpha + E1.z; c1.w = c1.w * alpha + E1.w;              \
            c2.x = c2.x * alpha + E2.x; c2.y = c2.y * alpha + E2.y;              \
            c2.z = c2.z * alpha + E2.z; c2.w = c2.w * alpha + E2.w;              \
            c3.x = c3.x * alpha + E3.x; c3.y = c3.y * alpha + E3.y;              \
            c3.z = c3.z * alpha + E3.z; c3.w = c3.w * alpha + E3.w;              \
        } else {                                                                 \
            const float p = __expf(d - m);                                       \
            s += p;                                                              \
            c0.x = fmaf(p, E0.x, c0.x); c0.y = fmaf(p, E0.y, c0.y);              \
            c0.z = fmaf(p, E0.z, c0.z); c0.w = fmaf(p, E0.w, c0.w);              \
            c1.x = fmaf(p, E1.x, c1.x); c1.y = fmaf(p, E1.y, c1.y);              \
            c1.z = fmaf(p, E1.z, c1.z); c1.w = fmaf(p, E1.w, c1.w);              \
            c2.x = fmaf(p, E2.x, c2.x); c2.y = fmaf(p, E2.y, c2.y);              \
            c2.z = fmaf(p, E2.z, c2.z); c2.w = fmaf(p, E2.w, c2.w);              \
            c3.x = fmaf(p, E3.x, c3.x); c3.y = fmaf(p, E3.y, c3.y);              \
            c3.z = fmaf(p, E3.z, c3.z); c3.w = fmaf(p, E3.w, c3.w);              \
        }                                                                        \
    }

__global__ __launch_bounds__(256) void k2_flash(const float* __restrict__ enc,
                                                const int* __restrict__ tgt_raw) {
    const int b = blockIdx.y;
    const int c = blockIdx.x;
    const int tid = threadIdx.x, w = tid >> 5, lane = tid & 31;

    __shared__ int s_is64;
    if (tid == 0) s_is64 = detect_is64(tgt_raw);
    __syncthreads();

    const int L = load_len(tgt_raw, b, s_is64);  // valid rows: t in [0, L)
    const int t0 = c * CHUNK;
    if (t0 >= L) {                               // entirely masked chunk
        if (tid == 0) g_ps[b * NCHUNK + c] = 0.f;
        return;
    }
    const int tend = min(t0 + CHUNK, L);

    // v[b] resident in registers for the whole chunk (L2-hit loads)
    const float4* v4 = (const float4*)(g_v + b * HH);
    const float4 va = v4[lane], vb = v4[lane + 32], vc = v4[lane + 64], vd = v4[lane + 96];

    float m = -INFINITY, s = 0.f;
    float4 c0 = make_float4(0.f, 0.f, 0.f, 0.f), c1 = c0, c2 = c0, c3 = c0;

    const float4* ebase = (const float4*)(enc + (size_t)b * TT * HH);

    // ---- depth-2 pipeline: stages A (t) and B (t+8); prefetch t+16/t+24 ----
    int t = t0 + w;
    float4 A0, A1, A2, A3, B0, B1, B2, B3;
    A0 = A1 = A2 = A3 = B0 = B1 = B2 = B3 = make_float4(0.f, 0.f, 0.f, 0.f);
    if (t < tend)     LOAD_ROW(A0, A1, A2, A3, t);
    if (t + 8 < tend) LOAD_ROW(B0, B1, B2, B3, t + 8);

    for (; t < tend; t += 16) {
        float4 C0 = A0, C1 = A1, C2 = A2, C3 = A3;
        float4 D0 = B0, D1 = B1, D2 = B2, D3 = B3;
        if (t + 16 < tend) LOAD_ROW(C0, C1, C2, C3, t + 16);
        if (t + 24 < tend) LOAD_ROW(D0, D1, D2, D3, t + 24);

        PROCESS_ROW(A0, A1, A2, A3);
        if (t + 8 < tend) PROCESS_ROW(B0, B1, B2, B3);

        A0 = C0; A1 = C1; A2 = C2; A3 = C3;
        B0 = D0; B1 = D1; B2 = D2; B3 = D3;
    }

    // ---- combine 8 warps inside the block ----
    __shared__ float sM[8], sS[8];
    __shared__ __align__(16) float sctx[8][HH];   // 16 KB
    float4* sc4 = (float4*)sctx[w];
    sc4[lane] = c0; sc4[lane + 32] = c1; sc4[lane + 64] = c2; sc4[lane + 96] = c3;
    if (lane == 0) { sM[w] = m; sS[w] = s; }
    __syncthreads();

    float M = -INFINITY;
#pragma unroll
    for (int i = 0; i < 8; i++) if (sS[i] > 0.f) M = fmaxf(M, sM[i]);
    float S = 0.f, f[8];
#pragma unroll
    for (int i = 0; i < 8; i++) {
        f[i] = (sS[i] > 0.f) ? __expf(sM[i] - M) : 0.f;
        S += sS[i] * f[i];
    }
    const int base = (b * NCHUNK + c) * HH;
    for (int h = tid; h < HH; h += 256) {
        float a = 0.f;
#pragma unroll
        for (int i = 0; i < 8; i++) a = fmaf(sctx[i][h], f[i], a);
        g_pctx[base + h] = a;
    }
    if (tid == 0) { g_pm[b * NCHUNK + c] = M; g_ps[b * NCHUNK + c] = S; }
}

// ---------------------------------------------------------------------------
// Kernel 3: combine the NCHUNK split-softmax partials per batch.
// ---------------------------------------------------------------------------
__global__ void k3_combine(float* __restrict__ out) {
    const int b = blockIdx.x, h = threadIdx.x;   // 512 threads
    float M = -INFINITY;
#pragma unroll
    for (int c = 0; c < NCHUNK; c++) {
        const float s = g_ps[b * NCHUNK + c];
        if (s > 0.f) M = fmaxf(M, g_pm[b * NCHUNK + c]);
    }
    float S = 0.f, acc = 0.f;
#pragma unroll
    for (int c = 0; c < NCHUNK; c++) {
        const float s = g_ps[b * NCHUNK + c];
        if (s > 0.f) {
            const float fct = __expf(g_pm[b * NCHUNK + c] - M);
            S += s * fct;
            acc = fmaf(g_pctx[(b * NCHUNK + c) * HH + h], fct, acc);
        }
    }
    out[b * HH + h] = acc / S;
}

// ---------------------------------------------------------------------------
extern "C" void kernel_launch(void* const* d_in, const int* in_sizes, int n_in,
                              void* d_out, int out_size) {
    const float* query = nullptr;
    const float* enc   = nullptr;
    const float* W     = nullptr;
    const int*   tgt   = nullptr;   // dtype (i32 vs i64) detected on device
    for (int i = 0; i < n_in; i++) {
        switch (in_sizes[i]) {
            case BB * QQ:               query = (const float*)d_in[i]; break;
            case BB * TT * HH:          enc   = (const float*)d_in[i]; break;
            case QQ * HH:               W     = (const float*)d_in[i]; break;
            case BB:                    tgt   = (const int*)d_in[i]; break;
            default: break;             // bias (512) unused: softmax-shift invariant
        }
    }

    k1_proj<<<dim3(HH / K1_HT, BB / K1_BGRP), 256>>>(query, W);
    k2_flash<<<dim3(NCHUNK, BB), 256>>>(enc, tgt);
    k3_combine<<<BB, HH>>>((float*)d_out);
}

// round 5
// speedup vs baseline: 1.1715x; 1.1715x over previous
#include <cuda_runtime.h>
#include <math.h>

#define BB 64
#define TT 2048
#define HH 512
#define QQ 512
#define NCHUNK 16
#define CHUNK (TT / NCHUNK)   // 128 rows per chunk
#define QSPLIT 8
#define QSEG (QQ / QSPLIT)    // 64

// Scratch (allocation-free rule: __device__ globals)
__device__ __align__(16) float g_vp[QSPLIT * BB * HH];   // partial v (2 MB)
__device__ float g_pm[BB * NCHUNK];                      // per-chunk running max
__device__ float g_ps[BB * NCHUNK];                      // per-chunk exp-sum
__device__ __align__(16) float g_pctx[BB * NCHUNK * HH]; // per-chunk weighted ctx (2 MB)

// ---------------------------------------------------------------------------
// tgt_index dtype detection (int64 vs int32) — verified working.
// ---------------------------------------------------------------------------
__device__ __forceinline__ int detect_is64(const int* __restrict__ tgt_raw) {
    int odd_or = 0;
#pragma unroll
    for (int i = 1; i < 2 * BB; i += 2) odd_or |= tgt_raw[i];
    return odd_or == 0;
}
__device__ __forceinline__ int load_len(const int* __restrict__ tgt_raw, int b, int is64) {
    return (is64 ? tgt_raw[2 * b] : tgt_raw[b]) + 1;
}

// ---------------------------------------------------------------------------
// Kernel 1: K-split partial matvec, max parallelism.
// grid (QSPLIT=8, BB=64) = 512 blocks, 128 threads. Block (qz,b): thread owns
// one float4 of h (coalesced W loads), 64-iter loop, 4 accumulators, ~30 regs.
// vp[qz][b][h] written; 8-way reduce folded into k2's v load (L2 hits).
// ---------------------------------------------------------------------------
__global__ __launch_bounds__(128) void k1_proj(const float* __restrict__ query,
                                               const float* __restrict__ W) {
    const int qz = blockIdx.x;
    const int b  = blockIdx.y;
    const int tid = threadIdx.x;          // h4 index: h = 4*tid .. 4*tid+3

    __shared__ float sq[QSEG];
    if (tid < QSEG) sq[tid] = query[b * QQ + qz * QSEG + tid];
    __syncthreads();

    const float4* W4 = (const float4*)W + (size_t)qz * QSEG * (HH / 4) + tid;
    float4 a = make_float4(0.f, 0.f, 0.f, 0.f);

#pragma unroll 16
    for (int q = 0; q < QSEG; q++) {
        const float4 w = W4[q * (HH / 4)];
        const float qv = sq[q];
        a.x = fmaf(w.x, qv, a.x);
        a.y = fmaf(w.y, qv, a.y);
        a.z = fmaf(w.z, qv, a.z);
        a.w = fmaf(w.w, qv, a.w);
    }

    ((float4*)g_vp)[((size_t)qz * BB + b) * (HH / 4) + tid] = a;
}

// ---------------------------------------------------------------------------
// Kernel 2: flash pass over one (chunk, batch). 8 warps, warp-per-row strided.
// v[b] reduced from the 8 K-split partials at block start (L2-hit loads).
// (Exact R3-passing structure: NCHUNK=16, depth-1 prefetch.)
// ---------------------------------------------------------------------------
__device__ __forceinline__ float dot4(float4 a, float4 b) {
    return a.x * b.x + a.y * b.y + a.z * b.z + a.w * b.w;
}

__global__ __launch_bounds__(256) void k2_flash(const float* __restrict__ enc,
                                                const int* __restrict__ tgt_raw) {
    const int b = blockIdx.y;
    const int c = blockIdx.x;
    const int tid = threadIdx.x, w = tid >> 5, lane = tid & 31;

    __shared__ int s_is64;
    if (tid == 0) s_is64 = detect_is64(tgt_raw);
    __syncthreads();

    const int L = load_len(tgt_raw, b, s_is64);  // valid rows: t in [0, L)
    const int t0 = c * CHUNK;
    if (t0 >= L) {                               // entirely masked chunk
        if (tid == 0) g_ps[b * NCHUNK + c] = 0.f;
        return;
    }
    const int tend = min(t0 + CHUNK, L);

    // v[b] = sum of QSPLIT partials, resident in registers for the whole chunk
    float4 va = make_float4(0.f, 0.f, 0.f, 0.f), vb = va, vc = va, vd = va;
#pragma unroll
    for (int z = 0; z < QSPLIT; z++) {
        const float4* vp = (const float4*)g_vp + ((size_t)z * BB + b) * (HH / 4);
        const float4 p0 = vp[lane], p1 = vp[lane + 32], p2 = vp[lane + 64], p3 = vp[lane + 96];
        va.x += p0.x; va.y += p0.y; va.z += p0.z; va.w += p0.w;
        vb.x += p1.x; vb.y += p1.y; vb.z += p1.z; vb.w += p1.w;
        vc.x += p2.x; vc.y += p2.y; vc.z += p2.z; vc.w += p2.w;
        vd.x += p3.x; vd.y += p3.y; vd.z += p3.z; vd.w += p3.w;
    }

    float m = -INFINITY, s = 0.f;
    float4 c0 = make_float4(0.f, 0.f, 0.f, 0.f), c1 = c0, c2 = c0, c3 = c0;

    const float4* ebase = (const float4*)(enc + (size_t)b * TT * HH);

    int t = t0 + w;
    float4 e0 = make_float4(0.f, 0.f, 0.f, 0.f), e1 = e0, e2 = e0, e3 = e0;
    if (t < tend) {
        const float4* r = ebase + (size_t)t * (HH / 4);
        e0 = r[lane]; e1 = r[lane + 32]; e2 = r[lane + 64]; e3 = r[lane + 96];
    }
    for (; t < tend; t += 8) {
        // prefetch next row (hide DRAM latency behind this row's math)
        float4 n0 = e0, n1 = e1, n2 = e2, n3 = e3;
        const int tn = t + 8;
        if (tn < tend) {
            const float4* r = ebase + (size_t)tn * (HH / 4);
            n0 = r[lane]; n1 = r[lane + 32]; n2 = r[lane + 64]; n3 = r[lane + 96];
        }
        // energy = enc_row . v   (16 FMA + 5 shfl)
        float d = dot4(e0, va) + dot4(e1, vb) + dot4(e2, vc) + dot4(e3, vd);
        d += __shfl_xor_sync(0xFFFFFFFFu, d, 16);
        d += __shfl_xor_sync(0xFFFFFFFFu, d, 8);
        d += __shfl_xor_sync(0xFFFFFFFFu, d, 4);
        d += __shfl_xor_sync(0xFFFFFFFFu, d, 2);
        d += __shfl_xor_sync(0xFFFFFFFFu, d, 1);

        if (d > m) {                      // new max (rare): rescale, p = 1
            const float alpha = __expf(m - d);   // exp(-inf)=0 handles first row
            m = d;
            s = s * alpha + 1.f;
            c0.x = c0.x * alpha + e0.x; c0.y = c0.y * alpha + e0.y;
            c0.z = c0.z * alpha + e0.z; c0.w = c0.w * alpha + e0.w;
            c1.x = c1.x * alpha + e1.x; c1.y = c1.y * alpha + e1.y;
            c1.z = c1.z * alpha + e1.z; c1.w = c1.w * alpha + e1.w;
            c2.x = c2.x * alpha + e2.x; c2.y = c2.y * alpha + e2.y;
            c2.z = c2.z * alpha + e2.z; c2.w = c2.w * alpha + e2.w;
            c3.x = c3.x * alpha + e3.x; c3.y = c3.y * alpha + e3.y;
            c3.z = c3.z * alpha + e3.z; c3.w = c3.w * alpha + e3.w;
        } else {                          // common path: 1 exp + 16 FMA
            const float p = __expf(d - m);
            s += p;
            c0.x = fmaf(p, e0.x, c0.x); c0.y = fmaf(p, e0.y, c0.y);
            c0.z = fmaf(p, e0.z, c0.z); c0.w = fmaf(p, e0.w, c0.w);
            c1.x = fmaf(p, e1.x, c1.x); c1.y = fmaf(p, e1.y, c1.y);
            c1.z = fmaf(p, e1.z, c1.z); c1.w = fmaf(p, e1.w, c1.w);
            c2.x = fmaf(p, e2.x, c2.x); c2.y = fmaf(p, e2.y, c2.y);
            c2.z = fmaf(p, e2.z, c2.z); c2.w = fmaf(p, e2.w, c2.w);
            c3.x = fmaf(p, e3.x, c3.x); c3.y = fmaf(p, e3.y, c3.y);
            c3.z = fmaf(p, e3.z, c3.z); c3.w = fmaf(p, e3.w, c3.w);
        }
        e0 = n0; e1 = n1; e2 = n2; e3 = n3;
    }

    // ---- combine 8 warps inside the block ----
    __shared__ float sM[8], sS[8];
    __shared__ __align__(16) float sctx[8][HH];   // 16 KB
    float4* sc4 = (float4*)sctx[w];
    sc4[lane] = c0; sc4[lane + 32] = c1; sc4[lane + 64] = c2; sc4[lane + 96] = c3;
    if (lane == 0) { sM[w] = m; sS[w] = s; }
    __syncthreads();

    float M = -INFINITY;
#pragma unroll
    for (int i = 0; i < 8; i++) if (sS[i] > 0.f) M = fmaxf(M, sM[i]);
    float S = 0.f, f[8];
#pragma unroll
    for (int i = 0; i < 8; i++) {
        f[i] = (sS[i] > 0.f) ? __expf(sM[i] - M) : 0.f;
        S += sS[i] * f[i];
    }
    const int base = (b * NCHUNK + c) * HH;
    for (int h = tid; h < HH; h += 256) {
        float a = 0.f;
#pragma unroll
        for (int i = 0; i < 8; i++) a = fmaf(sctx[i][h], f[i], a);
        g_pctx[base + h] = a;
    }
    if (tid == 0) { g_pm[b * NCHUNK + c] = M; g_ps[b * NCHUNK + c] = S; }
}

// ---------------------------------------------------------------------------
// Kernel 3: combine the NCHUNK split-softmax partials per batch.
// ---------------------------------------------------------------------------
__global__ void k3_combine(float* __restrict__ out) {
    const int b = blockIdx.x, h = threadIdx.x;   // 512 threads
    float M = -INFINITY;
#pragma unroll
    for (int c = 0; c < NCHUNK; c++) {
        const float s = g_ps[b * NCHUNK + c];
        if (s > 0.f) M = fmaxf(M, g_pm[b * NCHUNK + c]);
    }
    float S = 0.f, acc = 0.f;
#pragma unroll
    for (int c = 0; c < NCHUNK; c++) {
        const float s = g_ps[b * NCHUNK + c];
        if (s > 0.f) {
            const float fct = __expf(g_pm[b * NCHUNK + c] - M);
            S += s * fct;
            acc = fmaf(g_pctx[(b * NCHUNK + c) * HH + h], fct, acc);
        }
    }
    out[b * HH + h] = acc / S;
}

// ---------------------------------------------------------------------------
extern "C" void kernel_launch(void* const* d_in, const int* in_sizes, int n_in,
                              void* d_out, int out_size) {
    const float* query = nullptr;
    const float* enc   = nullptr;
    const float* W     = nullptr;
    const int*   tgt   = nullptr;   // dtype (i32 vs i64) detected on device
    for (int i = 0; i < n_in; i++) {
        switch (in_sizes[i]) {
            case BB * QQ:               query = (const float*)d_in[i]; break;
            case BB * TT * HH:          enc   = (const float*)d_in[i]; break;
            case QQ * HH:               W     = (const float*)d_in[i]; break;
            case BB:                    tgt   = (const int*)d_in[i]; break;
            default: break;             // bias (512) unused: softmax-shift invariant
        }
    }

    k1_proj<<<dim3(QSPLIT, BB), 128>>>(query, W);
    k2_flash<<<dim3(NCHUNK, BB), 256>>>(enc, tgt);
    k3_combine<<<BB, HH>>>((float*)d_out);
}

// round 6
// speedup vs baseline: 1.2242x; 1.0450x over previous
#include <cuda_runtime.h>
#include <math.h>

#define BB 64
#define TT 2048
#define HH 512
#define QQ 512
#define NCHUNK 16
#define CHUNK (TT / NCHUNK)   // 128 rows per chunk
#define QSPLIT 8
#define QSEG (QQ / QSPLIT)    // 64

// Scratch (allocation-free rule: __device__ globals)
__device__ __align__(16) float g_vp[QSPLIT * BB * HH];   // partial v (2 MB)
__device__ float g_pm[BB * NCHUNK];                      // per-chunk running max
__device__ float g_ps[BB * NCHUNK];                      // per-chunk exp-sum
__device__ __align__(16) float g_pctx[BB * NCHUNK * HH]; // per-chunk weighted ctx (2 MB)

// ---------------------------------------------------------------------------
// tgt_index dtype detection (int64 vs int32) — verified working.
// ---------------------------------------------------------------------------
__device__ __forceinline__ int detect_is64(const int* __restrict__ tgt_raw) {
    int odd_or = 0;
#pragma unroll
    for (int i = 1; i < 2 * BB; i += 2) odd_or |= tgt_raw[i];
    return odd_or == 0;
}
__device__ __forceinline__ int load_len(const int* __restrict__ tgt_raw, int b, int is64) {
    return (is64 ? tgt_raw[2 * b] : tgt_raw[b]) + 1;
}

// ---------------------------------------------------------------------------
// Kernel 1: K-split partial matvec with FORCED MLP.
// grid (QSPLIT=8, BB=64) = 512 blocks, 128 threads. Thread owns one float4 of
// h. Double-buffered batches of 8 float4 loads: next batch issued before the
// current batch's FMAs, guaranteeing 8-16 outstanding LDG.128 per thread.
// ---------------------------------------------------------------------------
#define K1_BATCH 8

__global__ __launch_bounds__(128) void k1_proj(const float* __restrict__ query,
                                               const float* __restrict__ W) {
    const int qz = blockIdx.x;
    const int b  = blockIdx.y;
    const int tid = threadIdx.x;          // h4 index: h = 4*tid .. 4*tid+3

    __shared__ float sq[QSEG];
    if (tid < QSEG) sq[tid] = query[b * QQ + qz * QSEG + tid];
    __syncthreads();

    const float4* W4 = (const float4*)W + (size_t)qz * QSEG * (HH / 4) + tid;
    float4 a = make_float4(0.f, 0.f, 0.f, 0.f);
    float4 b2 = make_float4(0.f, 0.f, 0.f, 0.f);   // 2nd accumulator: split FMA chain

    float4 cur[K1_BATCH], nxt[K1_BATCH];
#pragma unroll
    for (int i = 0; i < K1_BATCH; i++) cur[i] = W4[i * (HH / 4)];

#pragma unroll
    for (int qb = 0; qb < QSEG; qb += K1_BATCH) {
        if (qb + K1_BATCH < QSEG) {
#pragma unroll
            for (int i = 0; i < K1_BATCH; i++)
                nxt[i] = W4[(qb + K1_BATCH + i) * (HH / 4)];
        }
#pragma unroll
        for (int i = 0; i < K1_BATCH; i++) {
            const float qv = sq[qb + i];
            float4* acc = (i & 1) ? &b2 : &a;
            acc->x = fmaf(cur[i].x, qv, acc->x);
            acc->y = fmaf(cur[i].y, qv, acc->y);
            acc->z = fmaf(cur[i].z, qv, acc->z);
            acc->w = fmaf(cur[i].w, qv, acc->w);
        }
#pragma unroll
        for (int i = 0; i < K1_BATCH; i++) cur[i] = nxt[i];
    }

    a.x += b2.x; a.y += b2.y; a.z += b2.z; a.w += b2.w;
    ((float4*)g_vp)[((size_t)qz * BB + b) * (HH / 4) + tid] = a;
}

// ---------------------------------------------------------------------------
// Kernel 2: flash pass over one (chunk, batch). 8 warps, warp-per-row strided.
// v[b] reduced from the 8 K-split partials at block start (L2-hit loads).
// (Exact R5-passing structure: NCHUNK=16, depth-1 prefetch.)
// ---------------------------------------------------------------------------
__device__ __forceinline__ float dot4(float4 a, float4 b) {
    return a.x * b.x + a.y * b.y + a.z * b.z + a.w * b.w;
}

__global__ __launch_bounds__(256) void k2_flash(const float* __restrict__ enc,
                                                const int* __restrict__ tgt_raw) {
    const int b = blockIdx.y;
    const int c = blockIdx.x;
    const int tid = threadIdx.x, w = tid >> 5, lane = tid & 31;

    __shared__ int s_is64;
    if (tid == 0) s_is64 = detect_is64(tgt_raw);
    __syncthreads();

    const int L = load_len(tgt_raw, b, s_is64);  // valid rows: t in [0, L)
    const int t0 = c * CHUNK;
    if (t0 >= L) {                               // entirely masked chunk
        if (tid == 0) g_ps[b * NCHUNK + c] = 0.f;
        return;
    }
    const int tend = min(t0 + CHUNK, L);

    // v[b] = sum of QSPLIT partials, resident in registers for the whole chunk
    float4 va = make_float4(0.f, 0.f, 0.f, 0.f), vb = va, vc = va, vd = va;
#pragma unroll
    for (int z = 0; z < QSPLIT; z++) {
        const float4* vp = (const float4*)g_vp + ((size_t)z * BB + b) * (HH / 4);
        const float4 p0 = vp[lane], p1 = vp[lane + 32], p2 = vp[lane + 64], p3 = vp[lane + 96];
        va.x += p0.x; va.y += p0.y; va.z += p0.z; va.w += p0.w;
        vb.x += p1.x; vb.y += p1.y; vb.z += p1.z; vb.w += p1.w;
        vc.x += p2.x; vc.y += p2.y; vc.z += p2.z; vc.w += p2.w;
        vd.x += p3.x; vd.y += p3.y; vd.z += p3.z; vd.w += p3.w;
    }

    float m = -INFINITY, s = 0.f;
    float4 c0 = make_float4(0.f, 0.f, 0.f, 0.f), c1 = c0, c2 = c0, c3 = c0;

    const float4* ebase = (const float4*)(enc + (size_t)b * TT * HH);

    int t = t0 + w;
    float4 e0 = make_float4(0.f, 0.f, 0.f, 0.f), e1 = e0, e2 = e0, e3 = e0;
    if (t < tend) {
        const float4* r = ebase + (size_t)t * (HH / 4);
        e0 = r[lane]; e1 = r[lane + 32]; e2 = r[lane + 64]; e3 = r[lane + 96];
    }
    for (; t < tend; t += 8) {
        // prefetch next row (hide DRAM latency behind this row's math)
        float4 n0 = e0, n1 = e1, n2 = e2, n3 = e3;
        const int tn = t + 8;
        if (tn < tend) {
            const float4* r = ebase + (size_t)tn * (HH / 4);
            n0 = r[lane]; n1 = r[lane + 32]; n2 = r[lane + 64]; n3 = r[lane + 96];
        }
        // energy = enc_row . v   (16 FMA + 5 shfl)
        float d = dot4(e0, va) + dot4(e1, vb) + dot4(e2, vc) + dot4(e3, vd);
        d += __shfl_xor_sync(0xFFFFFFFFu, d, 16);
        d += __shfl_xor_sync(0xFFFFFFFFu, d, 8);
        d += __shfl_xor_sync(0xFFFFFFFFu, d, 4);
        d += __shfl_xor_sync(0xFFFFFFFFu, d, 2);
        d += __shfl_xor_sync(0xFFFFFFFFu, d, 1);

        if (d > m) {                      // new max (rare): rescale, p = 1
            const float alpha = __expf(m - d);   // exp(-inf)=0 handles first row
            m = d;
            s = s * alpha + 1.f;
            c0.x = c0.x * alpha + e0.x; c0.y = c0.y * alpha + e0.y;
            c0.z = c0.z * alpha + e0.z; c0.w = c0.w * alpha + e0.w;
            c1.x = c1.x * alpha + e1.x; c1.y = c1.y * alpha + e1.y;
            c1.z = c1.z * alpha + e1.z; c1.w = c1.w * alpha + e1.w;
            c2.x = c2.x * alpha + e2.x; c2.y = c2.y * alpha + e2.y;
            c2.z = c2.z * alpha + e2.z; c2.w = c2.w * alpha + e2.w;
            c3.x = c3.x * alpha + e3.x; c3.y = c3.y * alpha + e3.y;
            c3.z = c3.z * alpha + e3.z; c3.w = c3.w * alpha + e3.w;
        } else {                          // common path: 1 exp + 16 FMA
            const float p = __expf(d - m);
            s += p;
            c0.x = fmaf(p, e0.x, c0.x); c0.y = fmaf(p, e0.y, c0.y);
            c0.z = fmaf(p, e0.z, c0.z); c0.w = fmaf(p, e0.w, c0.w);
            c1.x = fmaf(p, e1.x, c1.x); c1.y = fmaf(p, e1.y, c1.y);
            c1.z = fmaf(p, e1.z, c1.z); c1.w = fmaf(p, e1.w, c1.w);
            c2.x = fmaf(p, e2.x, c2.x); c2.y = fmaf(p, e2.y, c2.y);
            c2.z = fmaf(p, e2.z, c2.z); c2.w = fmaf(p, e2.w, c2.w);
            c3.x = fmaf(p, e3.x, c3.x); c3.y = fmaf(p, e3.y, c3.y);
            c3.z = fmaf(p, e3.z, c3.z); c3.w = fmaf(p, e3.w, c3.w);
        }
        e0 = n0; e1 = n1; e2 = n2; e3 = n3;
    }

    // ---- combine 8 warps inside the block ----
    __shared__ float sM[8], sS[8];
    __shared__ __align__(16) float sctx[8][HH];   // 16 KB
    float4* sc4 = (float4*)sctx[w];
    sc4[lane] = c0; sc4[lane + 32] = c1; sc4[lane + 64] = c2; sc4[lane + 96] = c3;
    if (lane == 0) { sM[w] = m; sS[w] = s; }
    __syncthreads();

    float M = -INFINITY;
#pragma unroll
    for (int i = 0; i < 8; i++) if (sS[i] > 0.f) M = fmaxf(M, sM[i]);
    float S = 0.f, f[8];
#pragma unroll
    for (int i = 0; i < 8; i++) {
        f[i] = (sS[i] > 0.f) ? __expf(sM[i] - M) : 0.f;
        S += sS[i] * f[i];
    }
    const int base = (b * NCHUNK + c) * HH;
    for (int h = tid; h < HH; h += 256) {
        float a = 0.f;
#pragma unroll
        for (int i = 0; i < 8; i++) a = fmaf(sctx[i][h], f[i], a);
        g_pctx[base + h] = a;
    }
    if (tid == 0) { g_pm[b * NCHUNK + c] = M; g_ps[b * NCHUNK + c] = S; }
}

// ---------------------------------------------------------------------------
// Kernel 3: combine the NCHUNK split-softmax partials per batch.
// ---------------------------------------------------------------------------
__global__ void k3_combine(float* __restrict__ out) {
    const int b = blockIdx.x, h = threadIdx.x;   // 512 threads
    float M = -INFINITY;
#pragma unroll
    for (int c = 0; c < NCHUNK; c++) {
        const float s = g_ps[b * NCHUNK + c];
        if (s > 0.f) M = fmaxf(M, g_pm[b * NCHUNK + c]);
    }
    float S = 0.f, acc = 0.f;
#pragma unroll
    for (int c = 0; c < NCHUNK; c++) {
        const float s = g_ps[b * NCHUNK + c];
        if (s > 0.f) {
            const float fct = __expf(g_pm[b * NCHUNK + c] - M);
            S += s * fct;
            acc = fmaf(g_pctx[(b * NCHUNK + c) * HH + h], fct, acc);
        }
    }
    out[b * HH + h] = acc / S;
}

// ---------------------------------------------------------------------------
extern "C" void kernel_launch(void* const* d_in, const int* in_sizes, int n_in,
                              void* d_out, int out_size) {
    const float* query = nullptr;
    const float* enc   = nullptr;
    const float* W     = nullptr;
    const int*   tgt   = nullptr;   // dtype (i32 vs i64) detected on device
    for (int i = 0; i < n_in; i++) {
        switch (in_sizes[i]) {
            case BB * QQ:               query = (const float*)d_in[i]; break;
            case BB * TT * HH:          enc   = (const float*)d_in[i]; break;
            case QQ * HH:               W     = (const float*)d_in[i]; break;
            case BB:                    tgt   = (const int*)d_in[i]; break;
            default: break;             // bias (512) unused: softmax-shift invariant
        }
    }

    k1_proj<<<dim3(QSPLIT, BB), 128>>>(query, W);
    k2_flash<<<dim3(NCHUNK, BB), 256>>>(enc, tgt);
    k3_combine<<<BB, HH>>>((float*)d_out);
}

// round 7
// speedup vs baseline: 1.3359x; 1.0913x over previous
#include <cuda_runtime.h>
#include <math.h>

#define BB 64
#define TT 2048
#define HH 512
#define QQ 512
#define NCHUNK 16
#define CHUNK (TT / NCHUNK)   // 128 rows per chunk
#define QSPLIT 8
#define QSEG (QQ / QSPLIT)    // 64

// Scratch (allocation-free rule: __device__ globals)
__device__ __align__(16) float g_vp[QSPLIT * BB * HH];   // partial v (2 MB)
__device__ float g_pm[BB * NCHUNK];                      // per-chunk running max
__device__ float g_ps[BB * NCHUNK];                      // per-chunk exp-sum
__device__ __align__(16) float g_pctx[BB * NCHUNK * HH]; // per-chunk weighted ctx (2 MB)

// ---------------------------------------------------------------------------
// tgt_index dtype detection (int64 vs int32) — verified working.
// ---------------------------------------------------------------------------
__device__ __forceinline__ int detect_is64(const int* __restrict__ tgt_raw) {
    int odd_or = 0;
#pragma unroll
    for (int i = 1; i < 2 * BB; i += 2) odd_or |= tgt_raw[i];
    return odd_or == 0;
}
__device__ __forceinline__ int load_len(const int* __restrict__ tgt_raw, int b, int is64) {
    return (is64 ? tgt_raw[2 * b] : tgt_raw[b]) + 1;
}

// ---------------------------------------------------------------------------
// Kernel 1: K-split partial matvec with cp.async-staged W (MLP guaranteed by
// the async copy unit, not ptxas scheduling).
// grid (QSPLIT=8, BB/4=16) = 128 blocks, 128 threads. Block (qz, b0..b0+3):
// W slice [qz*64, qz*64+64) x 512 staged in 8 stages of 8 rows (16 KB),
// double-buffered. Thread owns h-float4 = tid; consumes only its own slots.
// ---------------------------------------------------------------------------
#define K1_BGRP   4
#define K1_ROWS   8
#define K1_STAGES (QSEG / K1_ROWS)   // 8

__device__ __forceinline__ void cpa16(void* smem, const void* gmem) {
    unsigned s = (unsigned)__cvta_generic_to_shared(smem);
    asm volatile("cp.async.cg.shared.global [%0], [%1], 16;" :: "r"(s), "l"(gmem));
}

__global__ __launch_bounds__(128) void k1_proj(const float* __restrict__ query,
                                               const float* __restrict__ W) {
    const int qz = blockIdx.x;
    const int b0 = blockIdx.y * K1_BGRP;
    const int tid = threadIdx.x;          // h4 index: h = 4*tid .. 4*tid+3

    __shared__ float sq[K1_BGRP][QSEG];                   // 1 KB
    __shared__ __align__(16) float4 sw[2][K1_ROWS * 128]; // 32 KB

    for (int i = tid; i < K1_BGRP * QSEG; i += 128)
        sq[i / QSEG][i % QSEG] = query[(b0 + i / QSEG) * QQ + qz * QSEG + (i % QSEG)];
    __syncthreads();

    const float4* Wg = (const float4*)W + (size_t)qz * QSEG * (HH / 4);

    // prefetch stage 0
#pragma unroll
    for (int k = 0; k < K1_ROWS; k++)
        cpa16(&sw[0][tid + k * 128], Wg + (tid + k * 128));
    asm volatile("cp.async.commit_group;");

    float4 a0 = make_float4(0.f, 0.f, 0.f, 0.f), a1 = a0, a2 = a0, a3 = a0;

#pragma unroll
    for (int s = 0; s < K1_STAGES; s++) {
        const int buf = s & 1;
        if (s + 1 < K1_STAGES) {
            const int nb = (s + 1) & 1;
            const float4* Ws = Wg + (s + 1) * K1_ROWS * 128;
#pragma unroll
            for (int k = 0; k < K1_ROWS; k++)
                cpa16(&sw[nb][tid + k * 128], Ws + (tid + k * 128));
            asm volatile("cp.async.commit_group;");
            asm volatile("cp.async.wait_group 1;");
        } else {
            asm volatile("cp.async.wait_group 0;");
        }
#pragma unroll
        for (int r = 0; r < K1_ROWS; r++) {
            const float4 w = sw[buf][r * 128 + tid];
            const int qi = s * K1_ROWS + r;
            const float q0 = sq[0][qi], q1 = sq[1][qi], q2 = sq[2][qi], q3 = sq[3][qi];
            a0.x = fmaf(w.x, q0, a0.x); a0.y = fmaf(w.y, q0, a0.y);
            a0.z = fmaf(w.z, q0, a0.z); a0.w = fmaf(w.w, q0, a0.w);
            a1.x = fmaf(w.x, q1, a1.x); a1.y = fmaf(w.y, q1, a1.y);
            a1.z = fmaf(w.z, q1, a1.z); a1.w = fmaf(w.w, q1, a1.w);
            a2.x = fmaf(w.x, q2, a2.x); a2.y = fmaf(w.y, q2, a2.y);
            a2.z = fmaf(w.z, q2, a2.z); a2.w = fmaf(w.w, q2, a2.w);
            a3.x = fmaf(w.x, q3, a3.x); a3.y = fmaf(w.y, q3, a3.y);
            a3.z = fmaf(w.z, q3, a3.z); a3.w = fmaf(w.w, q3, a3.w);
        }
    }

    float4* vp = (float4*)g_vp + (size_t)qz * BB * (HH / 4);
    vp[(b0 + 0) * (HH / 4) + tid] = a0;
    vp[(b0 + 1) * (HH / 4) + tid] = a1;
    vp[(b0 + 2) * (HH / 4) + tid] = a2;
    vp[(b0 + 3) * (HH / 4) + tid] = a3;
}

// ---------------------------------------------------------------------------
// Kernel 2: flash pass over one (chunk, batch). 8 warps, warp-per-row strided.
// v[b] reduced from the 8 K-split partials at block start (L2-hit loads).
// (Exact passing structure: NCHUNK=16, depth-1 prefetch.)
// ---------------------------------------------------------------------------
__device__ __forceinline__ float dot4(float4 a, float4 b) {
    return a.x * b.x + a.y * b.y + a.z * b.z + a.w * b.w;
}

__global__ __launch_bounds__(256) void k2_flash(const float* __restrict__ enc,
                                                const int* __restrict__ tgt_raw) {
    const int b = blockIdx.y;
    const int c = blockIdx.x;
    const int tid = threadIdx.x, w = tid >> 5, lane = tid & 31;

    __shared__ int s_is64;
    if (tid == 0) s_is64 = detect_is64(tgt_raw);
    __syncthreads();

    const int L = load_len(tgt_raw, b, s_is64);  // valid rows: t in [0, L)
    const int t0 = c * CHUNK;
    if (t0 >= L) {                               // entirely masked chunk
        if (tid == 0) g_ps[b * NCHUNK + c] = 0.f;
        return;
    }
    const int tend = min(t0 + CHUNK, L);

    // v[b] = sum of QSPLIT partials, resident in registers for the whole chunk
    float4 va = make_float4(0.f, 0.f, 0.f, 0.f), vb = va, vc = va, vd = va;
#pragma unroll
    for (int z = 0; z < QSPLIT; z++) {
        const float4* vp = (const float4*)g_vp + ((size_t)z * BB + b) * (HH / 4);
        const float4 p0 = vp[lane], p1 = vp[lane + 32], p2 = vp[lane + 64], p3 = vp[lane + 96];
        va.x += p0.x; va.y += p0.y; va.z += p0.z; va.w += p0.w;
        vb.x += p1.x; vb.y += p1.y; vb.z += p1.z; vb.w += p1.w;
        vc.x += p2.x; vc.y += p2.y; vc.z += p2.z; vc.w += p2.w;
        vd.x += p3.x; vd.y += p3.y; vd.z += p3.z; vd.w += p3.w;
    }

    float m = -INFINITY, s = 0.f;
    float4 c0 = make_float4(0.f, 0.f, 0.f, 0.f), c1 = c0, c2 = c0, c3 = c0;

    const float4* ebase = (const float4*)(enc + (size_t)b * TT * HH);

    int t = t0 + w;
    float4 e0 = make_float4(0.f, 0.f, 0.f, 0.f), e1 = e0, e2 = e0, e3 = e0;
    if (t < tend) {
        const float4* r = ebase + (size_t)t * (HH / 4);
        e0 = r[lane]; e1 = r[lane + 32]; e2 = r[lane + 64]; e3 = r[lane + 96];
    }
    for (; t < tend; t += 8) {
        // prefetch next row (hide DRAM latency behind this row's math)
        float4 n0 = e0, n1 = e1, n2 = e2, n3 = e3;
        const int tn = t + 8;
        if (tn < tend) {
            const float4* r = ebase + (size_t)tn * (HH / 4);
            n0 = r[lane]; n1 = r[lane + 32]; n2 = r[lane + 64]; n3 = r[lane + 96];
        }
        // energy = enc_row . v   (16 FMA + 5 shfl)
        float d = dot4(e0, va) + dot4(e1, vb) + dot4(e2, vc) + dot4(e3, vd);
        d += __shfl_xor_sync(0xFFFFFFFFu, d, 16);
        d += __shfl_xor_sync(0xFFFFFFFFu, d, 8);
        d += __shfl_xor_sync(0xFFFFFFFFu, d, 4);
        d += __shfl_xor_sync(0xFFFFFFFFu, d, 2);
        d += __shfl_xor_sync(0xFFFFFFFFu, d, 1);

        if (d > m) {                      // new max (rare): rescale, p = 1
            const float alpha = __expf(m - d);   // exp(-inf)=0 handles first row
            m = d;
            s = s * alpha + 1.f;
            c0.x = c0.x * alpha + e0.x; c0.y = c0.y * alpha + e0.y;
            c0.z = c0.z * alpha + e0.z; c0.w = c0.w * alpha + e0.w;
            c1.x = c1.x * alpha + e1.x; c1.y = c1.y * alpha + e1.y;
            c1.z = c1.z * alpha + e1.z; c1.w = c1.w * alpha + e1.w;
            c2.x = c2.x * alpha + e2.x; c2.y = c2.y * alpha + e2.y;
            c2.z = c2.z * alpha + e2.z; c2.w = c2.w * alpha + e2.w;
            c3.x = c3.x * alpha + e3.x; c3.y = c3.y * alpha + e3.y;
            c3.z = c3.z * alpha + e3.z; c3.w = c3.w * alpha + e3.w;
        } else {                          // common path: 1 exp + 16 FMA
            const float p = __expf(d - m);
            s += p;
            c0.x = fmaf(p, e0.x, c0.x); c0.y = fmaf(p, e0.y, c0.y);
            c0.z = fmaf(p, e0.z, c0.z); c0.w = fmaf(p, e0.w, c0.w);
            c1.x = fmaf(p, e1.x, c1.x); c1.y = fmaf(p, e1.y, c1.y);
            c1.z = fmaf(p, e1.z, c1.z); c1.w = fmaf(p, e1.w, c1.w);
            c2.x = fmaf(p, e2.x, c2.x); c2.y = fmaf(p, e2.y, c2.y);
            c2.z = fmaf(p, e2.z, c2.z); c2.w = fmaf(p, e2.w, c2.w);
            c3.x = fmaf(p, e3.x, c3.x); c3.y = fmaf(p, e3.y, c3.y);
            c3.z = fmaf(p, e3.z, c3.z); c3.w = fmaf(p, e3.w, c3.w);
        }
        e0 = n0; e1 = n1; e2 = n2; e3 = n3;
    }

    // ---- combine 8 warps inside the block ----
    __shared__ float sM[8], sS[8];
    __shared__ __align__(16) float sctx[8][HH];   // 16 KB
    float4* sc4 = (float4*)sctx[w];
    sc4[lane] = c0; sc4[lane + 32] = c1; sc4[lane + 64] = c2; sc4[lane + 96] = c3;
    if (lane == 0) { sM[w] = m; sS[w] = s; }
    __syncthreads();

    float M = -INFINITY;
#pragma unroll
    for (int i = 0; i < 8; i++) if (sS[i] > 0.f) M = fmaxf(M, sM[i]);
    float S = 0.f, f[8];
#pragma unroll
    for (int i = 0; i < 8; i++) {
        f[i] = (sS[i] > 0.f) ? __expf(sM[i] - M) : 0.f;
        S += sS[i] * f[i];
    }
    const int base = (b * NCHUNK + c) * HH;
    for (int h = tid; h < HH; h += 256) {
        float a = 0.f;
#pragma unroll
        for (int i = 0; i < 8; i++) a = fmaf(sctx[i][h], f[i], a);
        g_pctx[base + h] = a;
    }
    if (tid == 0) { g_pm[b * NCHUNK + c] = M; g_ps[b * NCHUNK + c] = S; }
}

// ---------------------------------------------------------------------------
// Kernel 3: combine the NCHUNK split-softmax partials per batch.
// ---------------------------------------------------------------------------
__global__ void k3_combine(float* __restrict__ out) {
    const int b = blockIdx.x, h = threadIdx.x;   // 512 threads
    float M = -INFINITY;
#pragma unroll
    for (int c = 0; c < NCHUNK; c++) {
        const float s = g_ps[b * NCHUNK + c];
        if (s > 0.f) M = fmaxf(M, g_pm[b * NCHUNK + c]);
    }
    float S = 0.f, acc = 0.f;
#pragma unroll
    for (int c = 0; c < NCHUNK; c++) {
        const float s = g_ps[b * NCHUNK + c];
        if (s > 0.f) {
            const float fct = __expf(g_pm[b * NCHUNK + c] - M);
            S += s * fct;
            acc = fmaf(g_pctx[(b * NCHUNK + c) * HH + h], fct, acc);
        }
    }
    out[b * HH + h] = acc / S;
}

// ---------------------------------------------------------------------------
extern "C" void kernel_launch(void* const* d_in, const int* in_sizes, int n_in,
                              void* d_out, int out_size) {
    const float* query = nullptr;
    const float* enc   = nullptr;
    const float* W     = nullptr;
    const int*   tgt   = nullptr;   // dtype (i32 vs i64) detected on device
    for (int i = 0; i < n_in; i++) {
        switch (in_sizes[i]) {
            case BB * QQ:               query = (const float*)d_in[i]; break;
            case BB * TT * HH:          enc   = (const float*)d_in[i]; break;
            case QQ * HH:               W     = (const float*)d_in[i]; break;
            case BB:                    tgt   = (const int*)d_in[i]; break;
            default: break;             // bias (512) unused: softmax-shift invariant
        }
    }

    k1_proj<<<dim3(QSPLIT, BB / K1_BGRP), 128>>>(query, W);
    k2_flash<<<dim3(NCHUNK, BB), 256>>>(enc, tgt);
    k3_combine<<<BB, HH>>>((float*)d_out);
}

// round 8
// speedup vs baseline: 1.5665x; 1.1727x over previous
#include <cuda_runtime.h>
#include <math.h>

#define BB 64
#define TT 2048
#define HH 512
#define QQ 512
#define NCHUNK 16
#define CHUNK (TT / NCHUNK)   // 128 rows per chunk
#define QSPLIT 8
#define QSEG (QQ / QSPLIT)    // 64

// Scratch (allocation-free rule: __device__ globals)
__device__ __align__(16) float g_vp[QSPLIT * BB * HH];   // partial v (2 MB)
__device__ float g_pm[BB * NCHUNK];                      // per-chunk running max
__device__ float g_ps[BB * NCHUNK];                      // per-chunk exp-sum
__device__ __align__(16) float g_pctx[BB * NCHUNK * HH]; // per-chunk weighted ctx (2 MB)

__device__ __forceinline__ int detect_is64(const int* __restrict__ tgt_raw) {
    int odd_or = 0;
#pragma unroll
    for (int i = 1; i < 2 * BB; i += 2) odd_or |= tgt_raw[i];
    return odd_or == 0;
}
__device__ __forceinline__ int load_len(const int* __restrict__ tgt_raw, int b, int is64) {
    return (is64 ? tgt_raw[2 * b] : tgt_raw[b]) + 1;
}

__device__ __forceinline__ void cpa16(void* smem, const void* gmem) {
    unsigned s = (unsigned)__cvta_generic_to_shared(smem);
    asm volatile("cp.async.cg.shared.global [%0], [%1], 16;" :: "r"(s), "l"(gmem));
}

// ---------------------------------------------------------------------------
// Kernel 1: K-split partial matvec, cp.async-staged W, depth-4 pipeline.
// grid (8, 16), 128 threads. 16 stages of 4 rows, 4 buffers (32 KB).
// Thread consumes only its own staged slots -> no barriers in loop.
// ---------------------------------------------------------------------------
#define K1_BGRP   4
#define K1_ROWS   4
#define K1_NBUF   4
#define K1_STAGES (QSEG / K1_ROWS)   // 16

__global__ __launch_bounds__(128) void k1_proj(const float* __restrict__ query,
                                               const float* __restrict__ W) {
    const int qz = blockIdx.x;
    const int b0 = blockIdx.y * K1_BGRP;
    const int tid = threadIdx.x;          // h4 index: h = 4*tid .. 4*tid+3

    __shared__ float sq[K1_BGRP][QSEG];                        // 1 KB
    __shared__ __align__(16) float4 sw[K1_NBUF][K1_ROWS * 128]; // 32 KB

    for (int i = tid; i < K1_BGRP * QSEG; i += 128)
        sq[i / QSEG][i % QSEG] = query[(b0 + i / QSEG) * QQ + qz * QSEG + (i % QSEG)];
    __syncthreads();

    const float4* Wg = (const float4*)W + (size_t)qz * QSEG * (HH / 4);

#pragma unroll
    for (int s = 0; s < K1_NBUF; s++) {
#pragma unroll
        for (int k = 0; k < K1_ROWS; k++)
            cpa16(&sw[s][tid + k * 128], Wg + (s * K1_ROWS + k) * 128 + tid);
        asm volatile("cp.async.commit_group;");
    }

    float4 a0 = make_float4(0.f, 0.f, 0.f, 0.f), a1 = a0, a2 = a0, a3 = a0;

#pragma unroll
    for (int s = 0; s < K1_STAGES; s++) {
        asm volatile("cp.async.wait_group %0;" :: "n"(K1_NBUF - 1));
        const int buf = s & (K1_NBUF - 1);
#pragma unroll
        for (int r = 0; r < K1_ROWS; r++) {
            const float4 w = sw[buf][r * 128 + tid];
            const int qi = s * K1_ROWS + r;
            const float q0 = sq[0][qi], q1 = sq[1][qi], q2 = sq[2][qi], q3 = sq[3][qi];
            a0.x = fmaf(w.x, q0, a0.x); a0.y = fmaf(w.y, q0, a0.y);
            a0.z = fmaf(w.z, q0, a0.z); a0.w = fmaf(w.w, q0, a0.w);
            a1.x = fmaf(w.x, q1, a1.x); a1.y = fmaf(w.y, q1, a1.y);
            a1.z = fmaf(w.z, q1, a1.z); a1.w = fmaf(w.w, q1, a1.w);
            a2.x = fmaf(w.x, q2, a2.x); a2.y = fmaf(w.y, q2, a2.y);
            a2.z = fmaf(w.z, q2, a2.z); a2.w = fmaf(w.w, q2, a2.w);
            a3.x = fmaf(w.x, q3, a3.x); a3.y = fmaf(w.y, q3, a3.y);
            a3.z = fmaf(w.z, q3, a3.z); a3.w = fmaf(w.w, q3, a3.w);
        }
        // refill this buffer with stage s+NBUF (empty commit past the end)
        if (s + K1_NBUF < K1_STAGES) {
            const float4* Ws = Wg + (size_t)(s + K1_NBUF) * K1_ROWS * 128;
#pragma unroll
            for (int k = 0; k < K1_ROWS; k++)
                cpa16(&sw[buf][tid + k * 128], Ws + k * 128 + tid);
        }
        asm volatile("cp.async.commit_group;");
    }

    float4* vp = (float4*)g_vp + (size_t)qz * BB * (HH / 4);
    vp[(b0 + 0) * (HH / 4) + tid] = a0;
    vp[(b0 + 1) * (HH / 4) + tid] = a1;
    vp[(b0 + 2) * (HH / 4) + tid] = a2;
    vp[(b0 + 3) * (HH / 4) + tid] = a3;
}

// ---------------------------------------------------------------------------
// Kernel 2: flash pass, per-warp barrier-free cp.async pipeline (NSTAGE=3).
// Warp w owns rows t0+w, t0+8+w, ... Each thread stages exactly the slots it
// reads: sbuf[st][w*128 + lane + k*32]. Combine arrays overlay drained sbuf.
// ---------------------------------------------------------------------------
#define K2_NSTAGE 3

__device__ __forceinline__ float dot4(float4 a, float4 b) {
    return a.x * b.x + a.y * b.y + a.z * b.z + a.w * b.w;
}

#define PROCESS_ROW(E0, E1, E2, E3)                                              \
    {                                                                            \
        float d = dot4(E0, va) + dot4(E1, vb) + dot4(E2, vc) + dot4(E3, vd);     \
        d += __shfl_xor_sync(0xFFFFFFFFu, d, 16);                                \
        d += __shfl_xor_sync(0xFFFFFFFFu, d, 8);                                 \
        d += __shfl_xor_sync(0xFFFFFFFFu, d, 4);                                 \
        d += __shfl_xor_sync(0xFFFFFFFFu, d, 2);                                 \
        d += __shfl_xor_sync(0xFFFFFFFFu, d, 1);                                 \
        if (d > m) {                                                             \
            const float alpha = __expf(m - d);                                   \
            m = d;                                                               \
            ssum = ssum * alpha + 1.f;                                           \
            c0.x = c0.x * alpha + E0.x; c0.y = c0.y * alpha + E0.y;              \
            c0.z = c0.z * alpha + E0.z; c0.w = c0.w * alpha + E0.w;              \
            c1.x = c1.x * alpha + E1.x; c1.y = c1.y * alpha + E1.y;              \
            c1.z = c1.z * alpha + E1.z; c1.w = c1.w * alpha + E1.w;              \
            c2.x = c2.x * alpha + E2.x; c2.y = c2.y * alpha + E2.y;              \
            c2.z = c2.z * alpha + E2.z; c2.w = c2.w * alpha + E2.w;              \
            c3.x = c3.x * alpha + E3.x; c3.y = c3.y * alpha + E3.y;              \
            c3.z = c3.z * alpha + E3.z; c3.w = c3.w * alpha + E3.w;              \
        } else {                                                                 \
            const float p = __expf(d - m);                                       \
            ssum += p;                                                           \
            c0.x = fmaf(p, E0.x, c0.x); c0.y = fmaf(p, E0.y, c0.y);              \
            c0.z = fmaf(p, E0.z, c0.z); c0.w = fmaf(p, E0.w, c0.w);              \
            c1.x = fmaf(p, E1.x, c1.x); c1.y = fmaf(p, E1.y, c1.y);              \
            c1.z = fmaf(p, E1.z, c1.z); c1.w = fmaf(p, E1.w, c1.w);              \
            c2.x = fmaf(p, E2.x, c2.x); c2.y = fmaf(p, E2.y, c2.y);              \
            c2.z = fmaf(p, E2.z, c2.z); c2.w = fmaf(p, E2.w, c2.w);              \
            c3.x = fmaf(p, E3.x, c3.x); c3.y = fmaf(p, E3.y, c3.y);              \
            c3.z = fmaf(p, E3.z, c3.z); c3.w = fmaf(p, E3.w, c3.w);              \
        }                                                                        \
    }

__global__ __launch_bounds__(256, 4) void k2_flash(const float* __restrict__ enc,
                                                   const int* __restrict__ tgt_raw) {
    __shared__ __align__(16) float4 sbuf[K2_NSTAGE][8 * 128];   // 48 KB (static max)

    const int b = blockIdx.y;
    const int c = blockIdx.x;
    const int tid = threadIdx.x, w = tid >> 5, lane = tid & 31;

    // dtype flag via sbuf scratch (free until prefetch)
    int* flag = (int*)&sbuf[0][0];
    if (tid == 0) *flag = detect_is64(tgt_raw);
    __syncthreads();
    const int is64 = *flag;
    __syncthreads();                             // everyone read before overwrite

    const int L = load_len(tgt_raw, b, is64);    // valid rows: t in [0, L)
    const int t0 = c * CHUNK;
    if (t0 >= L) {                               // entirely masked chunk
        if (tid == 0) g_ps[b * NCHUNK + c] = 0.f;
        return;
    }
    const int tend = min(t0 + CHUNK, L);
    const int total = (tend - t0 + 7) >> 3;      // stages for this block

    // v[b] = sum of QSPLIT partials (L1/L2-hit loads)
    float4 va = make_float4(0.f, 0.f, 0.f, 0.f), vb = va, vc = va, vd = va;
#pragma unroll
    for (int z = 0; z < QSPLIT; z++) {
        const float4* vp = (const float4*)g_vp + ((size_t)z * BB + b) * (HH / 4);
        const float4 p0 = vp[lane], p1 = vp[lane + 32], p2 = vp[lane + 64], p3 = vp[lane + 96];
        va.x += p0.x; va.y += p0.y; va.z += p0.z; va.w += p0.w;
        vb.x += p1.x; vb.y += p1.y; vb.z += p1.z; vb.w += p1.w;
        vc.x += p2.x; vc.y += p2.y; vc.z += p2.z; vc.w += p2.w;
        vd.x += p3.x; vd.y += p3.y; vd.z += p3.z; vd.w += p3.w;
    }

    const float4* ebase = (const float4*)enc + (size_t)b * TT * (HH / 4);

    // prefetch stages 0..2 (row t0 + st*8 + w; each thread stages what it reads)
#pragma unroll
    for (int st = 0; st < K2_NSTAGE; st++) {
        const int row = t0 + st * 8 + w;
        if (row < tend) {
            const float4* src = ebase + (size_t)row * 128;
#pragma unroll
            for (int k = 0; k < 4; k++)
                cpa16(&sbuf[st][w * 128 + lane + k * 32], src + lane + k * 32);
        }
        asm volatile("cp.async.commit_group;");
    }

    float m = -INFINITY, ssum = 0.f;
    float4 c0 = make_float4(0.f, 0.f, 0.f, 0.f), c1 = c0, c2 = c0, c3 = c0;

    for (int st = 0; st < total; st++) {
        asm volatile("cp.async.wait_group %0;" :: "n"(K2_NSTAGE - 1));
        const int buf = st % K2_NSTAGE;
        const int row = t0 + st * 8 + w;
        if (row < tend) {
            const float4 e0 = sbuf[buf][w * 128 + lane];
            const float4 e1 = sbuf[buf][w * 128 + lane + 32];
            const float4 e2 = sbuf[buf][w * 128 + lane + 64];
            const float4 e3 = sbuf[buf][w * 128 + lane + 96];
            PROCESS_ROW(e0, e1, e2, e3);
        }
        // refill this buffer with stage st+NSTAGE (empty commit past the end)
        const int row2 = t0 + (st + K2_NSTAGE) * 8 + w;
        if (row2 < tend) {
            const float4* src = ebase + (size_t)row2 * 128;
#pragma unroll
            for (int k = 0; k < 4; k++)
                cpa16(&sbuf[buf][w * 128 + lane + k * 32], src + lane + k * 32);
        }
        asm volatile("cp.async.commit_group;");
    }
    asm volatile("cp.async.wait_group 0;");
    __syncthreads();                              // pipeline drained; reuse sbuf

    // ---- combine 8 warps: overlay sctx/sM/sS on sbuf ----
    float* sctx = (float*)sbuf;                   // [8][512] = 16 KB
    float* sMv  = (float*)sbuf + 8 * HH;          // 8 floats (start of sbuf[1])
    float* sSv  = sMv + 8;

    float4* sc4 = (float4*)(sctx + w * HH);
    sc4[lane] = c0; sc4[lane + 32] = c1; sc4[lane + 64] = c2; sc4[lane + 96] = c3;
    if (lane == 0) { sMv[w] = m; sSv[w] = ssum; }
    __syncthreads();

    float M = -INFINITY;
#pragma unroll
    for (int i = 0; i < 8; i++) if (sSv[i] > 0.f) M = fmaxf(M, sMv[i]);
    float S = 0.f, f[8];
#pragma unroll
    for (int i = 0; i < 8; i++) {
        f[i] = (sSv[i] > 0.f) ? __expf(sMv[i] - M) : 0.f;
        S += sSv[i] * f[i];
    }
    const int base = (b * NCHUNK + c) * HH;
    for (int h = tid; h < HH; h += 256) {
        float a = 0.f;
#pragma unroll
        for (int i = 0; i < 8; i++) a = fmaf(sctx[i * HH + h], f[i], a);
        g_pctx[base + h] = a;
    }
    if (tid == 0) { g_pm[b * NCHUNK + c] = M; g_ps[b * NCHUNK + c] = S; }
}

// ---------------------------------------------------------------------------
// Kernel 3: combine the NCHUNK split-softmax partials per batch.
// ---------------------------------------------------------------------------
__global__ void k3_combine(float* __restrict__ out) {
    const int b = blockIdx.x, h = threadIdx.x;   // 512 threads
    float M = -INFINITY;
#pragma unroll
    for (int c = 0; c < NCHUNK; c++) {
        const float s = g_ps[b * NCHUNK + c];
        if (s > 0.f) M = fmaxf(M, g_pm[b * NCHUNK + c]);
    }
    float S = 0.f, acc = 0.f;
#pragma unroll
    for (int c = 0; c < NCHUNK; c++) {
        const float s = g_ps[b * NCHUNK + c];
        if (s > 0.f) {
            const float fct = __expf(g_pm[b * NCHUNK + c] - M);
            S += s * fct;
            acc = fmaf(g_pctx[(b * NCHUNK + c) * HH + h], fct, acc);
        }
    }
    out[b * HH + h] = acc / S;
}

// ---------------------------------------------------------------------------
extern "C" void kernel_launch(void* const* d_in, const int* in_sizes, int n_in,
                              void* d_out, int out_size) {
    const float* query = nullptr;
    const float* enc   = nullptr;
    const float* W     = nullptr;
    const int*   tgt   = nullptr;   // dtype (i32 vs i64) detected on device
    for (int i = 0; i < n_in; i++) {
        switch (in_sizes[i]) {
            case BB * QQ:               query = (const float*)d_in[i]; break;
            case BB * TT * HH:          enc   = (const float*)d_in[i]; break;
            case QQ * HH:               W     = (const float*)d_in[i]; break;
            case BB:                    tgt   = (const int*)d_in[i]; break;
            default: break;             // bias (512) unused: softmax-shift invariant
        }
    }

    k1_proj<<<dim3(QSPLIT, BB / K1_BGRP), 128>>>(query, W);
    k2_flash<<<dim3(NCHUNK, BB), 256>>>(enc, tgt);
    k3_combine<<<BB, HH>>>((float*)d_out);
}